// round 6
// baseline (speedup 1.0000x reference)
#include <cuda_runtime.h>

// Problem constants (match reference_code)
#define NN 4096   // batch
#define DD 8192   // feature dim
#define KE 0.14426950408889634f   // log2(e) / tau, tau = 10

__device__ __forceinline__ float ex2f(float x) {
    float y;
    asm("ex2.approx.ftz.f32 %0, %1;" : "=f"(y) : "f"(x));
    return y;
}

__device__ __forceinline__ float4 aquad(float4 v) {
    return make_float4(ex2f(v.x * v.x * KE), ex2f(v.y * v.y * KE),
                       ex2f(v.z * v.z * KE), ex2f(v.w * v.w * KE));
}
__device__ __forceinline__ float hsum4(float4 a) { return (a.x + a.y) + (a.z + a.w); }

__device__ __forceinline__ void maskacc(float4 a, uchar4 lb, unsigned char ml,
                                        int d0, int i, float& sB, int& cnt) {
    if (lb.x == ml && d0 + 0 != i) { sB += ex2f(a.x * KE); cnt++; }
    if (lb.y == ml && d0 + 1 != i) { sB += ex2f(a.y * KE); cnt++; }
    if (lb.z == ml && d0 + 2 != i) { sB += ex2f(a.z * KE); cnt++; }
    if (lb.w == ml && d0 + 3 != i) { sB += ex2f(a.w * KE); cnt++; }
}

__global__ __launch_bounds__(256) void supcon_kernel(const float* __restrict__ emb,
                                                     const long long* __restrict__ labels,
                                                     float* __restrict__ out) {
    __shared__ __align__(16) unsigned char slab[NN];
    __shared__ float sAsum[8], sAB[8], sBsum[8], sBB[8];
    __shared__ int   sAc[8], sBc[8];
    __shared__ float s_term[2];

    const int tid  = threadIdx.x;
    const int lane = tid & 31;
    const int wid  = tid >> 5;

    const int iA = blockIdx.x * 2;
    const int iB = iA + 1;

    // Build 4096-entry uint8 label table from int64 input (L2-resident)
    const longlong2* __restrict__ L2v = (const longlong2*)labels;
    #pragma unroll
    for (int k = 0; k < 8; k++) {
        const int idx = tid + k * 256;
        const longlong2 v = L2v[idx];
        slab[2 * idx + 0] = (unsigned char)v.x;
        slab[2 * idx + 1] = (unsigned char)v.y;
    }
    __syncthreads();

    const unsigned char lA = slab[iA];
    const unsigned char lB = slab[iB];
    const float4* __restrict__ rowA = (const float4*)(emb + (size_t)iA * DD);
    const float4* __restrict__ rowB = (const float4*)(emb + (size_t)iB * DD);
    const uchar4* __restrict__ slab4 = (const uchar4*)slab;

    float sumA = 0.0f, sumB = 0.0f;
    float bA = 0.0f, bB = 0.0f;
    int   cA = 0, cB = 0;

    // ================= first half: d in [0, NN) =================
    // Front-batch all 8 row loads (named scalars -> 8 LDG.128 in flight)
    {
        const float4 va0 = rowA[tid +   0];
        const float4 va1 = rowA[tid + 256];
        const float4 va2 = rowA[tid + 512];
        const float4 va3 = rowA[tid + 768];
        const float4 vb0 = rowB[tid +   0];
        const float4 vb1 = rowB[tid + 256];
        const float4 vb2 = rowB[tid + 512];
        const float4 vb3 = rowB[tid + 768];
        const uchar4 l0 = slab4[tid +   0];
        const uchar4 l1 = slab4[tid + 256];
        const uchar4 l2 = slab4[tid + 512];
        const uchar4 l3 = slab4[tid + 768];

        const float4 aa0 = aquad(va0), aa1 = aquad(va1), aa2 = aquad(va2), aa3 = aquad(va3);
        const float4 ab0 = aquad(vb0), ab1 = aquad(vb1), ab2 = aquad(vb2), ab3 = aquad(vb3);

        sumA += (hsum4(aa0) + hsum4(aa1)) + (hsum4(aa2) + hsum4(aa3));
        sumB += (hsum4(ab0) + hsum4(ab1)) + (hsum4(ab2) + hsum4(ab3));

        maskacc(aa0, l0, lA, (tid +   0) * 4, iA, bA, cA);
        maskacc(aa1, l1, lA, (tid + 256) * 4, iA, bA, cA);
        maskacc(aa2, l2, lA, (tid + 512) * 4, iA, bA, cA);
        maskacc(aa3, l3, lA, (tid + 768) * 4, iA, bA, cA);

        maskacc(ab0, l0, lB, (tid +   0) * 4, iB, bB, cB);
        maskacc(ab1, l1, lB, (tid + 256) * 4, iB, bB, cB);
        maskacc(ab2, l2, lB, (tid + 512) * 4, iB, bB, cB);
        maskacc(ab3, l3, lB, (tid + 768) * 4, iB, bB, cB);
    }

    // ================= second half: d in [NN, DD) =================
    {
        const float4 va0 = rowA[tid + 1024];
        const float4 va1 = rowA[tid + 1280];
        const float4 va2 = rowA[tid + 1536];
        const float4 va3 = rowA[tid + 1792];
        const float4 vb0 = rowB[tid + 1024];
        const float4 vb1 = rowB[tid + 1280];
        const float4 vb2 = rowB[tid + 1536];
        const float4 vb3 = rowB[tid + 1792];

        sumA += (hsum4(aquad(va0)) + hsum4(aquad(va1))) +
                (hsum4(aquad(va2)) + hsum4(aquad(va3)));
        sumB += (hsum4(aquad(vb0)) + hsum4(aquad(vb1))) +
                (hsum4(aquad(vb2)) + hsum4(aquad(vb3)));
    }

    // ---- intra-block reduce ----
    #pragma unroll
    for (int o = 16; o > 0; o >>= 1) {
        sumA += __shfl_down_sync(0xFFFFFFFFu, sumA, o);
        bA   += __shfl_down_sync(0xFFFFFFFFu, bA, o);
        cA   += __shfl_down_sync(0xFFFFFFFFu, cA, o);
        sumB += __shfl_down_sync(0xFFFFFFFFu, sumB, o);
        bB   += __shfl_down_sync(0xFFFFFFFFu, bB, o);
        cB   += __shfl_down_sync(0xFFFFFFFFu, cB, o);
    }
    if (lane == 0) {
        sAsum[wid] = sumA; sAB[wid] = bA; sAc[wid] = cA;
        sBsum[wid] = sumB; sBB[wid] = bB; sBc[wid] = cB;
    }
    __syncthreads();

    if (tid == 0) {
        float ts = 0.0f, tb = 0.0f;
        int   tc = 0;
        #pragma unroll
        for (int w = 0; w < 8; w++) { ts += sAsum[w]; tb += sAB[w]; tc += sAc[w]; }
        const float xd = emb[(size_t)iA * DD + iA];
        const float dn = ts - ex2f(xd * xd * KE);
        s_term[0] = __logf(tb / (dn * (float)tc));
    }
    if (tid == 32) {
        float ts = 0.0f, tb = 0.0f;
        int   tc = 0;
        #pragma unroll
        for (int w = 0; w < 8; w++) { ts += sBsum[w]; tb += sBB[w]; tc += sBc[w]; }
        const float xd = emb[(size_t)iB * DD + iB];
        const float dn = ts - ex2f(xd * xd * KE);
        s_term[1] = __logf(tb / (dn * (float)tc));
    }
    __syncthreads();

    if (tid == 0) atomicAdd(out, s_term[0] + s_term[1]);
}

extern "C" void kernel_launch(void* const* d_in, const int* in_sizes, int n_in,
                              void* d_out, int out_size) {
    const float*     emb    = (const float*)d_in[0];
    const long long* labels = (const long long*)d_in[1];
    float*           out    = (float*)d_out;

    cudaMemsetAsync(out, 0, sizeof(float));
    supcon_kernel<<<NN / 2, 256>>>(emb, labels, out);
}